// round 10
// baseline (speedup 1.0000x reference)
#include <cuda_runtime.h>
#include <cuda_fp16.h>
#include <cstdint>

#define T_TOKENS 4096
#define DM 512
#define NE 8
#define DF 2048
#define NPAIRS (T_TOKENS * 2)
#define MAX_T 80
#define NWORK 296     // persistent CTAs = 148 SMs x occupancy 2

// ---------------- device scratch ------------------------------------------
__device__ int   g_counts[NE];
__device__ int   g_cursor[NE];
__device__ int   g_offsets[NE + 1];
__device__ int   g_tok_e[NPAIRS];
__device__ float g_tok_g[NPAIRS];
__device__ int   g_row_tok[NPAIRS];
__device__ float g_row_gate[NPAIRS];
__device__ int2  g_tiles[MAX_T];
__device__ int   g_nt;
__device__ int   g_next;                          // dynamic tile counter
__device__ int   g_done4[MAX_T * 4];              // per (m, k-quarter) FFN1 done
__device__ __half g_xg[(size_t)NPAIRS * DM];      // 8 MiB gathered fp16 x
__device__ __half g_Y1[(size_t)NPAIRS * DF];      // 32 MiB
__device__ __half g_W1h[(size_t)NE * DM * DF];    // 16 MiB
__device__ __half g_W2h[(size_t)NE * DF * DM];    // 16 MiB

// ---------------- helpers ----------------------------------------------------
#define LDSM_X4(R, ADDR) \
    asm volatile("ldmatrix.sync.aligned.m8n8.x4.shared.b16 {%0,%1,%2,%3}, [%4];" \
        : "=r"((R)[0]), "=r"((R)[1]), "=r"((R)[2]), "=r"((R)[3]) : "r"(ADDR))

#define LDSM_X4T(R0, R1, R2, R3, ADDR) \
    asm volatile("ldmatrix.sync.aligned.m8n8.x4.trans.shared.b16 {%0,%1,%2,%3}, [%4];" \
        : "=r"(R0), "=r"(R1), "=r"(R2), "=r"(R3) : "r"(ADDR))

#define MMA_F16(C, A, B) \
    asm volatile("mma.sync.aligned.m16n8k16.row.col.f32.f16.f16.f32 " \
        "{%0,%1,%2,%3}, {%4,%5,%6,%7}, {%8,%9}, {%0,%1,%2,%3};" \
        : "+f"((C)[0]), "+f"((C)[1]), "+f"((C)[2]), "+f"((C)[3]) \
        : "r"((A)[0]), "r"((A)[1]), "r"((A)[2]), "r"((A)[3]), \
          "r"((B)[0]), "r"((B)[1]))

#define CP16(DST, SRC) \
    asm volatile("cp.async.cg.shared.global [%0], [%1], 16;" \
        :: "r"(DST), "l"(SRC))
#define CP_COMMIT() asm volatile("cp.async.commit_group;")
#define CP_WAIT(N)  asm volatile("cp.async.wait_group %0;" :: "n"(N))

// ---------------- gating ------------------------------------------------------
__global__ __launch_bounds__(256)
void gate_kernel(const float* __restrict__ x,
                 const float* __restrict__ Wg,
                 const float* __restrict__ bg) {
    __shared__ float sWgT[NE * DM];
    for (int i = threadIdx.x; i < DM * NE; i += blockDim.x) {
        int d = i >> 3, e = i & 7;
        sWgT[e * DM + d] = Wg[i];
    }
    __syncthreads();

    int warp = threadIdx.x >> 5, lane = threadIdx.x & 31;
    int t = blockIdx.x * 8 + warp;
    const float* xr = x + (size_t)t * DM;

    float lg[NE];
#pragma unroll
    for (int e = 0; e < NE; e++) lg[e] = 0.0f;
#pragma unroll
    for (int i = 0; i < DM / 32; i++) {
        int d = lane + 32 * i;
        float xv = xr[d];
#pragma unroll
        for (int e = 0; e < NE; e++)
            lg[e] = fmaf(xv, sWgT[e * DM + d], lg[e]);
    }
#pragma unroll
    for (int off = 16; off > 0; off >>= 1)
#pragma unroll
        for (int e = 0; e < NE; e++)
            lg[e] += __shfl_xor_sync(0xFFFFFFFFu, lg[e], off);

    if (lane == 0) {
#pragma unroll
        for (int e = 0; e < NE; e++) lg[e] += bg[e];
        int i0 = 0;
#pragma unroll
        for (int e = 1; e < NE; e++) if (lg[e] > lg[i0]) i0 = e;
        int i1 = (i0 == 0) ? 1 : 0;
#pragma unroll
        for (int e = 0; e < NE; e++)
            if (e != i0 && lg[e] > lg[i1]) i1 = e;
        float g0 = 1.0f / (1.0f + expf(lg[i1] - lg[i0]));
        float g1 = 1.0f - g0;
        g_tok_e[t * 2 + 0] = i0;  g_tok_g[t * 2 + 0] = g0;
        g_tok_e[t * 2 + 1] = i1;  g_tok_g[t * 2 + 1] = g1;
        atomicAdd(&g_counts[i0], 1);
        atomicAdd(&g_counts[i1], 1);
    }
}

__global__ void prefix_kernel() {
    if (threadIdx.x != 0) return;
    int acc = 0;
#pragma unroll
    for (int e = 0; e < NE; e++) { g_offsets[e] = acc; acc += g_counts[e]; }
    g_offsets[NE] = acc;
    int n = 0;
    for (int e = 0; e < NE; e++)
        for (int m0 = 0; m0 < g_counts[e]; m0 += 128) {
            int2 v; v.x = e; v.y = m0; g_tiles[n++] = v;
        }
    g_nt = n;
}

__global__ void scatter_kernel() {
    int p = blockIdx.x * blockDim.x + threadIdx.x;
    if (p >= NPAIRS) return;
    int e = g_tok_e[p];
    int pos = atomicAdd(&g_cursor[e], 1);
    int row = g_offsets[e] + pos;
    g_row_tok[row]  = p >> 1;
    g_row_gate[row] = g_tok_g[p];
}

// ---------------- convert: W1, W2 fp16 + gathered x rows ---------------------
__global__ void convert_all(const float* __restrict__ W1,
                            const float* __restrict__ W2,
                            const float* __restrict__ x) {
    constexpr int NW = NE * DM * DF / 4;
    constexpr int NX = NPAIRS * DM / 4;
    int idx = blockIdx.x * blockDim.x + threadIdx.x;
    const float* srcp;
    __half* dst;
    if (idx < NW) {
        srcp = W1 + (size_t)idx * 4;  dst = g_W1h + (size_t)idx * 4;
    } else if (idx < 2 * NW) {
        int i = idx - NW;
        srcp = W2 + (size_t)i * 4;    dst = g_W2h + (size_t)i * 4;
    } else if (idx < 2 * NW + NX) {
        int i = idx - 2 * NW;
        int row = i >> 7, c4 = i & 127;          // DM/4 = 128
        int tok = g_row_tok[row];
        srcp = x + (size_t)tok * DM + (size_t)c4 * 4;
        dst  = g_xg + (size_t)row * DM + (size_t)c4 * 4;
    } else return;
    float4 v = *reinterpret_cast<const float4*>(srcp);
    __half2 a = __floats2half2_rn(v.x, v.y);
    __half2 b = __floats2half2_rn(v.z, v.w);
    uint2 o;
    o.x = *reinterpret_cast<uint32_t*>(&a);
    o.y = *reinterpret_cast<uint32_t*>(&b);
    *reinterpret_cast<uint2*>(dst) = o;
}

// ---------------- persistent fused FFN1+FFN2 ---------------------------------
// Dynamic tiles, uniform quantum: 128 M x 128 N x 512 K (16 chunks of BK=32).
//  t < g_nt*16        : FFN1 (m = t/16, nb = t%16): Y1 = relu(xg@W1+b1),
//                       then g_done4[m*4 + nb/4] += 1.
//  t >= g_nt*16       : FFN2 split-K piece (m = u/16, nb2 = u%4, ks = (u%16)/4):
//                       out[token] += gate * (Y1[.,ks*512:]@W2[ks*512:,nb2] +
//                       (ks==0 ? b2 : 0)), after spin g_done4[m*4+ks]==4.
// Deadlock-free: NWORK=296 <= resident capacity; FIFO ensures producers of any
// spinning consumer are already running.
__global__ __launch_bounds__(256, 2)
void moe_fused(const float* __restrict__ b1, const float* __restrict__ b2,
               float* __restrict__ out)
{
    constexpr int A_SZ = 128 * 40;
    constexpr int B_SZ = 32 * 136;
    constexpr int BUF  = A_SZ + B_SZ;

    __shared__ int s_tile;
    extern __shared__ __half smraw[];
    const uint32_t sbase = (uint32_t)__cvta_generic_to_shared(smraw);

    const int tid  = threadIdx.x;
    const int lane = tid & 31;
    const int warp = tid >> 5;
    const int wm = (warp & 3) * 32;
    const int wn = (warp >> 2) * 64;
    const uint32_t aoff = (uint32_t)((wm + (lane & 15)) * 40 + (lane >> 4) * 8);
    const uint32_t boff = (uint32_t)((((lane >> 3) & 1) * 8 + (lane & 7)) * 136
                                     + wn + (lane >> 4) * 8);

    for (;;) {
        __syncthreads();                     // smem/s_tile reuse barrier
        if (tid == 0) s_tile = atomicAdd(&g_next, 1);
        __syncthreads();
        const int t = s_tile;
        const int total1 = g_nt * 16;
        if (t >= 2 * total1) return;

        const bool is1 = t < total1;
        const int u = is1 ? t : t - total1;
        const int m_idx = u >> 4;
        const int sub = u & 15;
        const int2 te = g_tiles[m_idx];
        const int e = te.x, m0 = te.y;
        const int seg_start = g_offsets[e];
        const int seg_count = g_offsets[e + 1] - seg_start;

        int n0, k0, N_TOT, aStride;
        const __half *Ap, *Bp;
        if (is1) {
            n0 = sub * 128; k0 = 0; N_TOT = DF; aStride = DM;
            Ap = g_xg;
            Bp = g_W1h + (size_t)e * DM * DF + n0;
        } else {
            const int nb2 = sub & 3, ks = sub >> 2;
            n0 = nb2 * 128; k0 = ks * 512; N_TOT = DM; aStride = DF;
            Ap = g_Y1;
            Bp = g_W2h + (size_t)e * DF * DM + (size_t)k0 * DM + n0;
            if (tid == 0) {
                const int* fp = g_done4 + m_idx * 4 + ks;
                int fv;
                do { asm volatile("ld.global.cg.b32 %0, [%1];" : "=r"(fv) : "l"(fp)); }
                while (fv < 4);
            }
            __syncthreads();
            __threadfence();
        }
        const int ksel = is1 ? 0 : (sub >> 2);   // for bias gating

        uint32_t a_soff[2];
        size_t   a_gidx[2];
#pragma unroll
        for (int it = 0; it < 2; it++) {
            int uu = tid + it * 256;
            int r = m0 + (uu >> 2);
            if (r >= seg_count) r = seg_count - 1;
            a_soff[it] = (uint32_t)((uu >> 2) * 40 + (uu & 3) * 8) * 2;
            a_gidx[it] = (size_t)(seg_start + r) * aStride + k0 + (uu & 3) * 8;
        }
        uint32_t b_soff[2];
        size_t   b_gidx[2];
#pragma unroll
        for (int it = 0; it < 2; it++) {
            int v = tid + it * 256;
            int bk = v >> 4, bn = (v & 15) * 8;
            b_soff[it] = (uint32_t)(A_SZ + bk * 136 + bn) * 2;
            b_gidx[it] = (size_t)bk * N_TOT + bn;
        }

        float c[16][4];
#pragma unroll
        for (int f = 0; f < 16; f++)
#pragma unroll
            for (int q = 0; q < 4; q++) c[f][q] = 0.0f;

#define ISSUE(KC, BS) do { \
    uint32_t base_ = sbase + (uint32_t)(BS) * (BUF * 2); \
    _Pragma("unroll") \
    for (int it = 0; it < 2; it++) \
        CP16(base_ + a_soff[it], Ap + a_gidx[it] + (size_t)(KC) * 32); \
    _Pragma("unroll") \
    for (int it = 0; it < 2; it++) \
        CP16(base_ + b_soff[it], Bp + b_gidx[it] + (size_t)((KC) * 32) * N_TOT); \
} while (0)

#define COMPUTE(BS) do { \
    uint32_t base_ = sbase + (uint32_t)(BS) * (BUF * 2); \
    _Pragma("unroll") \
    for (int kt = 0; kt < 2; kt++) { \
        uint32_t ah[2][4]; \
        _Pragma("unroll") \
        for (int mt = 0; mt < 2; mt++) { \
            uint32_t ad = base_ + 2u * (aoff + (uint32_t)(mt * 640 + kt * 16)); \
            LDSM_X4(ah[mt], ad); \
        } \
        uint32_t bh[8][2]; \
        _Pragma("unroll") \
        for (int bt = 0; bt < 4; bt++) { \
            uint32_t bd = base_ + 2u * ((uint32_t)A_SZ + boff \
                                        + (uint32_t)(bt * 16 + kt * 16 * 136)); \
            LDSM_X4T(bh[bt * 2][0], bh[bt * 2][1], bh[bt * 2 + 1][0], bh[bt * 2 + 1][1], bd); \
        } \
        _Pragma("unroll") \
        for (int mt = 0; mt < 2; mt++) { \
            _Pragma("unroll") \
            for (int nt = 0; nt < 8; nt++) \
                MMA_F16(c[mt * 8 + nt], ah[mt], bh[nt]); \
        } \
    } \
} while (0)

        // ---- 4-stage cp.async pipeline, fixed 16 chunks ----
        ISSUE(0, 0); CP_COMMIT();
        ISSUE(1, 1); CP_COMMIT();
        ISSUE(2, 2); CP_COMMIT();
#pragma unroll 4
        for (int kc = 0; kc < 16; kc++) {
            if (kc < 14)       { CP_WAIT(2); }
            else if (kc == 14) { CP_WAIT(1); }
            else               { CP_WAIT(0); }
            __syncthreads();
            if (kc + 3 < 16) { ISSUE(kc + 3, (kc + 3) & 3); CP_COMMIT(); }
            COMPUTE(kc & 3);
        }

#undef ISSUE
#undef COMPUTE

        // ---- epilogue ----
        const int rbase = m0 + wm + (lane >> 2);
        if (is1) {
            const float* bp = b1 + (size_t)e * DF + n0;
#pragma unroll
            for (int mt = 0; mt < 2; mt++) {
#pragma unroll
                for (int nt = 0; nt < 8; nt++) {
                    float* cc = c[mt * 8 + nt];
                    int col = wn + nt * 8 + 2 * (lane & 3);
                    float2 bb = *reinterpret_cast<const float2*>(bp + col);
#pragma unroll
                    for (int h = 0; h < 2; h++) {
                        int r = rbase + mt * 16 + h * 8;
                        if (r < seg_count) {
                            float v0 = fmaxf(cc[h * 2 + 0] + bb.x, 0.0f);
                            float v1 = fmaxf(cc[h * 2 + 1] + bb.y, 0.0f);
                            __half2 hv = __floats2half2_rn(v0, v1);
                            size_t off = (size_t)(seg_start + r) * DF + n0 + col;
                            *reinterpret_cast<uint32_t*>(g_Y1 + off) =
                                *reinterpret_cast<uint32_t*>(&hv);
                        }
                    }
                }
            }
            __syncthreads();
            if (tid == 0) {
                __threadfence();
                atomicAdd(&g_done4[m_idx * 4 + (sub >> 2)], 1);
            }
        } else {
            const float* bp = b2 + (size_t)e * DM + n0;
#pragma unroll
            for (int mt = 0; mt < 2; mt++) {
#pragma unroll
                for (int nt = 0; nt < 8; nt++) {
                    float* cc = c[mt * 8 + nt];
                    int col = wn + nt * 8 + 2 * (lane & 3);
                    float2 bb;
                    bb.x = 0.0f; bb.y = 0.0f;
                    if (ksel == 0) bb = *reinterpret_cast<const float2*>(bp + col);
#pragma unroll
                    for (int h = 0; h < 2; h++) {
                        int r = rbase + mt * 16 + h * 8;
                        if (r < seg_count) {
                            int grow = seg_start + r;
                            int tok  = g_row_tok[grow];
                            float gg = g_row_gate[grow];
                            float* po = out + (size_t)tok * DM + n0 + col;
                            atomicAdd(po,     gg * (cc[h * 2 + 0] + bb.x));
                            atomicAdd(po + 1, gg * (cc[h * 2 + 1] + bb.y));
                        }
                    }
                }
            }
        }
    }
}

// ---------------- launch ------------------------------------------------------
extern "C" void kernel_launch(void* const* d_in, const int* in_sizes, int n_in,
                              void* d_out, int out_size) {
    const float* x  = (const float*)d_in[0];
    const float* Wg = (const float*)d_in[1];
    const float* bg = (const float*)d_in[2];
    const float* W1 = (const float*)d_in[3];
    const float* b1 = (const float*)d_in[4];
    const float* W2 = (const float*)d_in[5];
    const float* b2 = (const float*)d_in[6];
    float* out = (float*)d_out;

    constexpr int SMEM = 4 * (128 * 40 + 32 * 136) * 2;   // 75776
    cudaFuncSetAttribute(moe_fused,
                         cudaFuncAttributeMaxDynamicSharedMemorySize, SMEM);

    void *p_counts, *p_cursor, *p_done, *p_next;
    cudaGetSymbolAddress(&p_counts, g_counts);
    cudaGetSymbolAddress(&p_cursor, g_cursor);
    cudaGetSymbolAddress(&p_done,   g_done4);
    cudaGetSymbolAddress(&p_next,   g_next);

    cudaMemsetAsync(d_out, 0, (size_t)out_size * sizeof(float));
    cudaMemsetAsync(p_counts, 0, NE * sizeof(int));
    cudaMemsetAsync(p_cursor, 0, NE * sizeof(int));
    cudaMemsetAsync(p_done,   0, MAX_T * 4 * sizeof(int));
    cudaMemsetAsync(p_next,   0, sizeof(int));

    gate_kernel<<<T_TOKENS / 8, 256>>>(x, Wg, bg);
    prefix_kernel<<<1, 32>>>();
    scatter_kernel<<<NPAIRS / 256, 256>>>();
    constexpr int CTOT = (2 * NE * DM * DF + NPAIRS * DM) / 4;
    convert_all<<<(CTOT + 255) / 256, 256>>>(W1, W2, x);

    moe_fused<<<NWORK, 256, SMEM>>>(b1, b2, out);
}

// round 11
// speedup vs baseline: 1.2586x; 1.2586x over previous
#include <cuda_runtime.h>
#include <cuda_fp16.h>
#include <cstdint>

#define T_TOKENS 4096
#define DM 512
#define NE 8
#define DF 2048
#define NPAIRS (T_TOKENS * 2)
#define MAX_T 80      // >= 8192/128 + 8

// ---------------- device scratch ------------------------------------------
__device__ int   g_counts[NE];
__device__ int   g_cursor[NE];
__device__ int   g_offsets[NE + 1];
__device__ int   g_tok_e[NPAIRS];
__device__ float g_tok_g[NPAIRS];
__device__ int   g_row_tok[NPAIRS];
__device__ float g_row_gate[NPAIRS];
__device__ int2  g_tiles[MAX_T];
__device__ int   g_nt;
__device__ __half g_xg[(size_t)NPAIRS * DM];      // 8 MiB gathered fp16 x
__device__ __half g_Y1[(size_t)NPAIRS * DF];      // 32 MiB
__device__ __half g_W1h[(size_t)NE * DM * DF];    // 16 MiB
__device__ __half g_W2h[(size_t)NE * DF * DM];    // 16 MiB

// ---------------- helpers ----------------------------------------------------
#define LDSM_X4(R, ADDR) \
    asm volatile("ldmatrix.sync.aligned.m8n8.x4.shared.b16 {%0,%1,%2,%3}, [%4];" \
        : "=r"((R)[0]), "=r"((R)[1]), "=r"((R)[2]), "=r"((R)[3]) : "r"(ADDR))

#define LDSM_X4T(R0, R1, R2, R3, ADDR) \
    asm volatile("ldmatrix.sync.aligned.m8n8.x4.trans.shared.b16 {%0,%1,%2,%3}, [%4];" \
        : "=r"(R0), "=r"(R1), "=r"(R2), "=r"(R3) : "r"(ADDR))

#define MMA_F16(C, A, B) \
    asm volatile("mma.sync.aligned.m16n8k16.row.col.f32.f16.f16.f32 " \
        "{%0,%1,%2,%3}, {%4,%5,%6,%7}, {%8,%9}, {%0,%1,%2,%3};" \
        : "+f"((C)[0]), "+f"((C)[1]), "+f"((C)[2]), "+f"((C)[3]) \
        : "r"((A)[0]), "r"((A)[1]), "r"((A)[2]), "r"((A)[3]), \
          "r"((B)[0]), "r"((B)[1]))

#define CP16(DST, SRC) \
    asm volatile("cp.async.cg.shared.global [%0], [%1], 16;" \
        :: "r"(DST), "l"(SRC))
#define CP_COMMIT() asm volatile("cp.async.commit_group;")
#define CP_WAIT(N)  asm volatile("cp.async.wait_group %0;" :: "n"(N))

// ---------------- gating: warp per token, conflict-free ---------------------
__global__ __launch_bounds__(256)
void gate_kernel(const float* __restrict__ x,
                 const float* __restrict__ Wg,
                 const float* __restrict__ bg) {
    __shared__ float sWgT[NE * DM];   // transposed [e][d], 16 KB
    for (int i = threadIdx.x; i < DM * NE; i += blockDim.x) {
        int d = i >> 3, e = i & 7;
        sWgT[e * DM + d] = Wg[i];
    }
    __syncthreads();

    int warp = threadIdx.x >> 5, lane = threadIdx.x & 31;
    int t = blockIdx.x * 8 + warp;
    const float* xr = x + (size_t)t * DM;

    float lg[NE];
#pragma unroll
    for (int e = 0; e < NE; e++) lg[e] = 0.0f;
#pragma unroll
    for (int i = 0; i < DM / 32; i++) {
        int d = lane + 32 * i;
        float xv = xr[d];
#pragma unroll
        for (int e = 0; e < NE; e++)
            lg[e] = fmaf(xv, sWgT[e * DM + d], lg[e]);
    }
#pragma unroll
    for (int off = 16; off > 0; off >>= 1)
#pragma unroll
        for (int e = 0; e < NE; e++)
            lg[e] += __shfl_xor_sync(0xFFFFFFFFu, lg[e], off);

    if (lane == 0) {
#pragma unroll
        for (int e = 0; e < NE; e++) lg[e] += bg[e];
        int i0 = 0;
#pragma unroll
        for (int e = 1; e < NE; e++) if (lg[e] > lg[i0]) i0 = e;
        int i1 = (i0 == 0) ? 1 : 0;
#pragma unroll
        for (int e = 0; e < NE; e++)
            if (e != i0 && lg[e] > lg[i1]) i1 = e;
        float g0 = 1.0f / (1.0f + expf(lg[i1] - lg[i0]));
        float g1 = 1.0f - g0;
        g_tok_e[t * 2 + 0] = i0;  g_tok_g[t * 2 + 0] = g0;
        g_tok_e[t * 2 + 1] = i1;  g_tok_g[t * 2 + 1] = g1;
        atomicAdd(&g_counts[i0], 1);
        atomicAdd(&g_counts[i1], 1);
    }
}

// prefix sums + exact M=128 tile table
__global__ void prefix_kernel() {
    if (threadIdx.x != 0) return;
    int acc = 0;
#pragma unroll
    for (int e = 0; e < NE; e++) { g_offsets[e] = acc; acc += g_counts[e]; }
    g_offsets[NE] = acc;
    int n = 0;
    for (int e = 0; e < NE; e++)
        for (int m0 = 0; m0 < g_counts[e]; m0 += 128) {
            int2 v; v.x = e; v.y = m0; g_tiles[n++] = v;
        }
    g_nt = n;
}

// ---------------- scatter: slot assignment only ------------------------------
__global__ void scatter_kernel() {
    int p = blockIdx.x * blockDim.x + threadIdx.x;
    if (p >= NPAIRS) return;
    int e = g_tok_e[p];
    int pos = atomicAdd(&g_cursor[e], 1);
    int row = g_offsets[e] + pos;
    g_row_tok[row]  = p >> 1;
    g_row_gate[row] = g_tok_g[p];
}

// ---------------- convert: W1, W2 -> fp16; x -> gathered fp16 rows ----------
__global__ void convert_all(const float* __restrict__ W1,
                            const float* __restrict__ W2,
                            const float* __restrict__ x) {
    constexpr int NW = NE * DM * DF / 4;
    constexpr int NX = NPAIRS * DM / 4;
    int idx = blockIdx.x * blockDim.x + threadIdx.x;
    const float* srcp;
    __half* dst;
    if (idx < NW) {
        srcp = W1 + (size_t)idx * 4;  dst = g_W1h + (size_t)idx * 4;
    } else if (idx < 2 * NW) {
        int i = idx - NW;
        srcp = W2 + (size_t)i * 4;    dst = g_W2h + (size_t)i * 4;
    } else if (idx < 2 * NW + NX) {
        int i = idx - 2 * NW;
        int row = i >> 7, c4 = i & 127;          // DM/4 = 128
        int tok = g_row_tok[row];
        srcp = x + (size_t)tok * DM + (size_t)c4 * 4;
        dst  = g_xg + (size_t)row * DM + (size_t)c4 * 4;
    } else return;
    float4 v = *reinterpret_cast<const float4*>(srcp);
    __half2 a = __floats2half2_rn(v.x, v.y);
    __half2 b = __floats2half2_rn(v.z, v.w);
    uint2 o;
    o.x = *reinterpret_cast<uint32_t*>(&a);
    o.y = *reinterpret_cast<uint32_t*>(&b);
    *reinterpret_cast<uint2*>(dst) = o;
}

// ---------------- fp16 HMMA grouped GEMM (round-7 proven code) ---------------
// CTA tile 128x128, BK=32, 256 threads, warp tile 32x64, cp.async 4-stage,
// 2 CTAs/SM.  IS1=1: Y1 = relu(g_xg@W1+b1) fp16.
// IS1=0: out[token] += gate * (Y1@W2 + b2) via atomicAdd (fused combine).
template<int K_TOTAL, int N_TOTAL, int IS1>
__global__ __launch_bounds__(256, 2)
void moe_mma(const float* __restrict__ bias, float* __restrict__ out)
{
    constexpr int NC   = K_TOTAL / 32;
    constexpr int A_SZ = 128 * 40;               // elems
    constexpr int B_SZ = 32 * 136;               // elems
    constexpr int BUF  = A_SZ + B_SZ;            // 9472 elems

    if (blockIdx.x >= g_nt) return;
    const int2 te = g_tiles[blockIdx.x];
    const int e = te.x, m0 = te.y;
    const int seg_start = g_offsets[e];
    const int seg_count = g_offsets[e + 1] - seg_start;
    const int n0 = blockIdx.y * 128;

    const int tid  = threadIdx.x;
    const int lane = tid & 31;
    const int warp = tid >> 5;
    const int wm = (warp & 3) * 32;
    const int wn = (warp >> 2) * 64;

    extern __shared__ __half smraw[];
    const uint32_t sbase = (uint32_t)__cvta_generic_to_shared(smraw);

    const __half* Ap = IS1 ? g_xg : g_Y1;
    const __half* Bp = (IS1 ? g_W1h : g_W2h)
                       + (size_t)e * K_TOTAL * N_TOTAL + n0;

    uint32_t a_soff[2];
    size_t   a_gidx[2];
#pragma unroll
    for (int it = 0; it < 2; it++) {
        int u = tid + it * 256;                  // 512 int4 per A tile
        int r = m0 + (u >> 2);
        if (r >= seg_count) r = seg_count - 1;
        a_soff[it] = (uint32_t)((u >> 2) * 40 + (u & 3) * 8) * 2;
        a_gidx[it] = (size_t)(seg_start + r) * K_TOTAL + (u & 3) * 8;
    }
    uint32_t b_soff[2];
    size_t   b_gidx[2];
#pragma unroll
    for (int it = 0; it < 2; it++) {
        int v = tid + it * 256;                  // 512 int4 for B
        int bk = v >> 4, bn = (v & 15) * 8;
        b_soff[it] = (uint32_t)(A_SZ + bk * 136 + bn) * 2;
        b_gidx[it] = (size_t)bk * N_TOTAL + bn;
    }

    const uint32_t aoff = (uint32_t)((wm + (lane & 15)) * 40 + (lane >> 4) * 8);
    const uint32_t boff = (uint32_t)((((lane >> 3) & 1) * 8 + (lane & 7)) * 136
                                     + wn + (lane >> 4) * 8);

    float c[16][4];
#pragma unroll
    for (int f = 0; f < 16; f++)
#pragma unroll
        for (int q = 0; q < 4; q++) c[f][q] = 0.0f;

#define ISSUE(KC, BS) do { \
    uint32_t base_ = sbase + (uint32_t)(BS) * (BUF * 2); \
    _Pragma("unroll") \
    for (int it = 0; it < 2; it++) \
        CP16(base_ + a_soff[it], Ap + a_gidx[it] + (size_t)(KC) * 32); \
    _Pragma("unroll") \
    for (int it = 0; it < 2; it++) \
        CP16(base_ + b_soff[it], Bp + b_gidx[it] + (size_t)(KC) * 32 * N_TOTAL); \
} while (0)

#define COMPUTE(BS) do { \
    uint32_t base_ = sbase + (uint32_t)(BS) * (BUF * 2); \
    _Pragma("unroll") \
    for (int kt = 0; kt < 2; kt++) { \
        uint32_t ah[2][4]; \
        _Pragma("unroll") \
        for (int mt = 0; mt < 2; mt++) { \
            uint32_t ad = base_ + 2u * (aoff + (uint32_t)(mt * 640 + kt * 16)); \
            LDSM_X4(ah[mt], ad); \
        } \
        uint32_t bh[8][2]; \
        _Pragma("unroll") \
        for (int bt = 0; bt < 4; bt++) { \
            uint32_t bd = base_ + 2u * ((uint32_t)A_SZ + boff \
                                        + (uint32_t)(bt * 16 + kt * 16 * 136)); \
            LDSM_X4T(bh[bt * 2][0], bh[bt * 2][1], bh[bt * 2 + 1][0], bh[bt * 2 + 1][1], bd); \
        } \
        _Pragma("unroll") \
        for (int mt = 0; mt < 2; mt++) { \
            _Pragma("unroll") \
            for (int nt = 0; nt < 8; nt++) \
                MMA_F16(c[mt * 8 + nt], ah[mt], bh[nt]); \
        } \
    } \
} while (0)

    // ---- 4-stage cp.async pipeline ----
    ISSUE(0, 0); CP_COMMIT();
    ISSUE(1, 1); CP_COMMIT();
    ISSUE(2, 2); CP_COMMIT();
    for (int kc = 0; kc < NC; kc++) {
        if (kc < NC - 2)       { CP_WAIT(2); }
        else if (kc == NC - 2) { CP_WAIT(1); }
        else                   { CP_WAIT(0); }
        __syncthreads();
        if (kc + 3 < NC) { ISSUE(kc + 3, (kc + 3) & 3); CP_COMMIT(); }
        COMPUTE(kc & 3);
    }

#undef ISSUE
#undef COMPUTE

    // ---- epilogue ----
    const float* bp = bias + (size_t)e * N_TOTAL + n0;
    const int rbase = m0 + wm + (lane >> 2);
#pragma unroll
    for (int mt = 0; mt < 2; mt++) {
#pragma unroll
        for (int nt = 0; nt < 8; nt++) {
            float* cc = c[mt * 8 + nt];
            int col = wn + nt * 8 + 2 * (lane & 3);
            float2 bb = *reinterpret_cast<const float2*>(bp + col);
#pragma unroll
            for (int h = 0; h < 2; h++) {
                int r = rbase + mt * 16 + h * 8;
                if (r < seg_count) {
                    float v0 = cc[h * 2 + 0] + bb.x;
                    float v1 = cc[h * 2 + 1] + bb.y;
                    if (IS1) {
                        v0 = fmaxf(v0, 0.0f);
                        v1 = fmaxf(v1, 0.0f);
                        __half2 hv = __floats2half2_rn(v0, v1);
                        size_t off = (size_t)(seg_start + r) * DF + n0 + col;
                        *reinterpret_cast<uint32_t*>(g_Y1 + off) =
                            *reinterpret_cast<uint32_t*>(&hv);
                    } else {
                        int grow = seg_start + r;
                        int tok  = g_row_tok[grow];
                        float gg = g_row_gate[grow];
                        float* po = out + (size_t)tok * DM + n0 + col;
                        atomicAdd(po,     gg * v0);
                        atomicAdd(po + 1, gg * v1);
                    }
                }
            }
        }
    }
}

// ---------------- launch ------------------------------------------------------
extern "C" void kernel_launch(void* const* d_in, const int* in_sizes, int n_in,
                              void* d_out, int out_size) {
    const float* x  = (const float*)d_in[0];
    const float* Wg = (const float*)d_in[1];
    const float* bg = (const float*)d_in[2];
    const float* W1 = (const float*)d_in[3];
    const float* b1 = (const float*)d_in[4];
    const float* W2 = (const float*)d_in[5];
    const float* b2 = (const float*)d_in[6];
    float* out = (float*)d_out;

    constexpr int SMEM = 4 * (128 * 40 + 32 * 136) * 2;   // 75776
    cudaFuncSetAttribute(moe_mma<DM, DF, 1>,
                         cudaFuncAttributeMaxDynamicSharedMemorySize, SMEM);
    cudaFuncSetAttribute(moe_mma<DF, DM, 0>,
                         cudaFuncAttributeMaxDynamicSharedMemorySize, SMEM);

    void *p_counts, *p_cursor;
    cudaGetSymbolAddress(&p_counts, g_counts);
    cudaGetSymbolAddress(&p_cursor, g_cursor);

    cudaMemsetAsync(d_out, 0, (size_t)out_size * sizeof(float));
    cudaMemsetAsync(p_counts, 0, NE * sizeof(int));
    cudaMemsetAsync(p_cursor, 0, NE * sizeof(int));

    gate_kernel<<<T_TOKENS / 8, 256>>>(x, Wg, bg);
    prefix_kernel<<<1, 32>>>();
    scatter_kernel<<<NPAIRS / 256, 256>>>();
    constexpr int CTOT = (2 * NE * DM * DF + NPAIRS * DM) / 4;
    convert_all<<<(CTOT + 255) / 256, 256>>>(W1, W2, x);

    dim3 grid1(72, DF / 128);    // exact tile table, M=128
    moe_mma<DM, DF, 1><<<grid1, 256, SMEM>>>(b1, out);

    dim3 grid2(72, DM / 128);    // fused combine epilogue
    moe_mma<DF, DM, 0><<<grid2, 256, SMEM>>>(b2, out);
}

// round 12
// speedup vs baseline: 1.3399x; 1.0647x over previous
#include <cuda_runtime.h>
#include <cuda_fp16.h>
#include <cstdint>

#define T_TOKENS 4096
#define DM 512
#define NE 8
#define DF 2048
#define NPAIRS (T_TOKENS * 2)
#define MAX_T 80      // >= 8192/128 + 8

// ---------------- device scratch ------------------------------------------
__device__ int   g_ctrl[2 * NE];                  // [0,8)=counts, [8,16)=cursor
__device__ int   g_offsets[NE + 1];
__device__ int   g_tok_e[NPAIRS];
__device__ float g_tok_g[NPAIRS];
__device__ int   g_row_tok[NPAIRS];
__device__ float g_row_gate[NPAIRS];
__device__ int2  g_tiles[MAX_T];
__device__ int   g_nt;
__device__ __half g_xg[(size_t)NPAIRS * DM];      // 8 MiB gathered fp16 x
__device__ __half g_Y1[(size_t)NPAIRS * DF];      // 32 MiB
__device__ __half g_W1h[(size_t)NE * DM * DF];    // 16 MiB
__device__ __half g_W2h[(size_t)NE * DF * DM];    // 16 MiB

// ---------------- helpers ----------------------------------------------------
#define LDSM_X4(R, ADDR) \
    asm volatile("ldmatrix.sync.aligned.m8n8.x4.shared.b16 {%0,%1,%2,%3}, [%4];" \
        : "=r"((R)[0]), "=r"((R)[1]), "=r"((R)[2]), "=r"((R)[3]) : "r"(ADDR))

#define LDSM_X4T(R0, R1, R2, R3, ADDR) \
    asm volatile("ldmatrix.sync.aligned.m8n8.x4.trans.shared.b16 {%0,%1,%2,%3}, [%4];" \
        : "=r"(R0), "=r"(R1), "=r"(R2), "=r"(R3) : "r"(ADDR))

#define MMA_F16(C, A, B) \
    asm volatile("mma.sync.aligned.m16n8k16.row.col.f32.f16.f16.f32 " \
        "{%0,%1,%2,%3}, {%4,%5,%6,%7}, {%8,%9}, {%0,%1,%2,%3};" \
        : "+f"((C)[0]), "+f"((C)[1]), "+f"((C)[2]), "+f"((C)[3]) \
        : "r"((A)[0]), "r"((A)[1]), "r"((A)[2]), "r"((A)[3]), \
          "r"((B)[0]), "r"((B)[1]))

#define CP16(DST, SRC) \
    asm volatile("cp.async.cg.shared.global [%0], [%1], 16;" \
        :: "r"(DST), "l"(SRC))
#define CP_COMMIT() asm volatile("cp.async.commit_group;")
#define CP_WAIT(N)  asm volatile("cp.async.wait_group %0;" :: "n"(N))

__device__ __forceinline__ void cvt4(const float* srcp, __half* dst) {
    float4 v = *reinterpret_cast<const float4*>(srcp);
    __half2 a = __floats2half2_rn(v.x, v.y);
    __half2 b = __floats2half2_rn(v.z, v.w);
    uint2 o;
    o.x = *reinterpret_cast<uint32_t*>(&a);
    o.y = *reinterpret_cast<uint32_t*>(&b);
    *reinterpret_cast<uint2*>(dst) = o;
}

// ---------------- gate (blocks 0..511) + W convert (blocks 512..) -----------
// Gate blocks also zero their 8 token rows of out (replaces d_out memset).
#define GATE_BLKS 512
#define CVT_BLKS  ((2 * NE * DM * DF / 4) / 256)   // 16384

__global__ __launch_bounds__(256)
void gatecvt_kernel(const float* __restrict__ x,
                    const float* __restrict__ Wg,
                    const float* __restrict__ bg,
                    const float* __restrict__ W1,
                    const float* __restrict__ W2,
                    float* __restrict__ out) {
    const int bid = blockIdx.x;
    if (bid >= GATE_BLKS) {
        // ---- W conversion ----
        constexpr int NW = NE * DM * DF / 4;
        int idx = (bid - GATE_BLKS) * 256 + threadIdx.x;
        if (idx < NW) cvt4(W1 + (size_t)idx * 4, g_W1h + (size_t)idx * 4);
        else          cvt4(W2 + (size_t)(idx - NW) * 4, g_W2h + (size_t)(idx - NW) * 4);
        return;
    }

    // ---- zero this block's 8 output token rows (1024 float4) ----
    {
        float4 z; z.x = z.y = z.z = z.w = 0.0f;
        float4* ob = reinterpret_cast<float4*>(out) + (size_t)bid * 1024;
#pragma unroll
        for (int i = 0; i < 4; i++) ob[threadIdx.x + 256 * i] = z;
    }

    // ---- gating: warp per token ----
    __shared__ float sWgT[NE * DM];   // transposed [e][d]
    for (int i = threadIdx.x; i < DM * NE; i += blockDim.x) {
        int d = i >> 3, e = i & 7;
        sWgT[e * DM + d] = Wg[i];
    }
    __syncthreads();

    int warp = threadIdx.x >> 5, lane = threadIdx.x & 31;
    int t = bid * 8 + warp;
    const float* xr = x + (size_t)t * DM;

    float lg[NE];
#pragma unroll
    for (int e = 0; e < NE; e++) lg[e] = 0.0f;
#pragma unroll
    for (int i = 0; i < DM / 32; i++) {
        int d = lane + 32 * i;
        float xv = xr[d];
#pragma unroll
        for (int e = 0; e < NE; e++)
            lg[e] = fmaf(xv, sWgT[e * DM + d], lg[e]);
    }
#pragma unroll
    for (int off = 16; off > 0; off >>= 1)
#pragma unroll
        for (int e = 0; e < NE; e++)
            lg[e] += __shfl_xor_sync(0xFFFFFFFFu, lg[e], off);

    if (lane == 0) {
#pragma unroll
        for (int e = 0; e < NE; e++) lg[e] += bg[e];
        int i0 = 0;
#pragma unroll
        for (int e = 1; e < NE; e++) if (lg[e] > lg[i0]) i0 = e;
        int i1 = (i0 == 0) ? 1 : 0;
#pragma unroll
        for (int e = 0; e < NE; e++)
            if (e != i0 && lg[e] > lg[i1]) i1 = e;
        float g0 = 1.0f / (1.0f + expf(lg[i1] - lg[i0]));
        float g1 = 1.0f - g0;
        g_tok_e[t * 2 + 0] = i0;  g_tok_g[t * 2 + 0] = g0;
        g_tok_e[t * 2 + 1] = i1;  g_tok_g[t * 2 + 1] = g1;
        atomicAdd(&g_ctrl[i0], 1);
        atomicAdd(&g_ctrl[i1], 1);
    }
}

// prefix sums + exact M=128 tile table
__global__ void prefix_kernel() {
    if (threadIdx.x != 0) return;
    int acc = 0;
#pragma unroll
    for (int e = 0; e < NE; e++) { g_offsets[e] = acc; acc += g_ctrl[e]; }
    g_offsets[NE] = acc;
    int n = 0;
    for (int e = 0; e < NE; e++)
        for (int m0 = 0; m0 < g_ctrl[e]; m0 += 128) {
            int2 v; v.x = e; v.y = m0; g_tiles[n++] = v;
        }
    g_nt = n;
}

// ---------------- scatter: slot assignment only ------------------------------
__global__ void scatter_kernel() {
    int p = blockIdx.x * blockDim.x + threadIdx.x;
    if (p >= NPAIRS) return;
    int e = g_tok_e[p];
    int pos = atomicAdd(&g_ctrl[NE + e], 1);
    int row = g_offsets[e] + pos;
    g_row_tok[row]  = p >> 1;
    g_row_gate[row] = g_tok_g[p];
}

// ---------------- gather x rows -> fp16 (2 rows per 256-thread block) -------
__global__ __launch_bounds__(256)
void gatherx_kernel(const float* __restrict__ x) {
    int row = blockIdx.x * 2 + (threadIdx.x >> 7);
    int c4  = threadIdx.x & 127;                 // DM/4 = 128
    int tok = g_row_tok[row];
    cvt4(x + (size_t)tok * DM + (size_t)c4 * 4,
         g_xg + (size_t)row * DM + (size_t)c4 * 4);
}

// ---------------- fp16 HMMA grouped GEMM (round-7 proven code) ---------------
// CTA tile 128x128, BK=32, 256 threads, warp tile 32x64, cp.async 4-stage,
// 2 CTAs/SM.  IS1=1: Y1 = relu(g_xg@W1+b1) fp16.
// IS1=0: out[token] += gate * (Y1@W2 + b2) via atomicAdd (fused combine).
template<int K_TOTAL, int N_TOTAL, int IS1>
__global__ __launch_bounds__(256, 2)
void moe_mma(const float* __restrict__ bias, float* __restrict__ out)
{
    constexpr int NC   = K_TOTAL / 32;
    constexpr int A_SZ = 128 * 40;               // elems
    constexpr int B_SZ = 32 * 136;               // elems
    constexpr int BUF  = A_SZ + B_SZ;            // 9472 elems

    if (blockIdx.x >= g_nt) return;
    const int2 te = g_tiles[blockIdx.x];
    const int e = te.x, m0 = te.y;
    const int seg_start = g_offsets[e];
    const int seg_count = g_offsets[e + 1] - seg_start;
    const int n0 = blockIdx.y * 128;

    const int tid  = threadIdx.x;
    const int lane = tid & 31;
    const int warp = tid >> 5;
    const int wm = (warp & 3) * 32;
    const int wn = (warp >> 2) * 64;

    extern __shared__ __half smraw[];
    const uint32_t sbase = (uint32_t)__cvta_generic_to_shared(smraw);

    const __half* Ap = IS1 ? g_xg : g_Y1;
    const __half* Bp = (IS1 ? g_W1h : g_W2h)
                       + (size_t)e * K_TOTAL * N_TOTAL + n0;

    uint32_t a_soff[2];
    size_t   a_gidx[2];
#pragma unroll
    for (int it = 0; it < 2; it++) {
        int u = tid + it * 256;                  // 512 int4 per A tile
        int r = m0 + (u >> 2);
        if (r >= seg_count) r = seg_count - 1;
        a_soff[it] = (uint32_t)((u >> 2) * 40 + (u & 3) * 8) * 2;
        a_gidx[it] = (size_t)(seg_start + r) * K_TOTAL + (u & 3) * 8;
    }
    uint32_t b_soff[2];
    size_t   b_gidx[2];
#pragma unroll
    for (int it = 0; it < 2; it++) {
        int v = tid + it * 256;                  // 512 int4 for B
        int bk = v >> 4, bn = (v & 15) * 8;
        b_soff[it] = (uint32_t)(A_SZ + bk * 136 + bn) * 2;
        b_gidx[it] = (size_t)bk * N_TOTAL + bn;
    }

    const uint32_t aoff = (uint32_t)((wm + (lane & 15)) * 40 + (lane >> 4) * 8);
    const uint32_t boff = (uint32_t)((((lane >> 3) & 1) * 8 + (lane & 7)) * 136
                                     + wn + (lane >> 4) * 8);

    float c[16][4];
#pragma unroll
    for (int f = 0; f < 16; f++)
#pragma unroll
        for (int q = 0; q < 4; q++) c[f][q] = 0.0f;

#define ISSUE(KC, BS) do { \
    uint32_t base_ = sbase + (uint32_t)(BS) * (BUF * 2); \
    _Pragma("unroll") \
    for (int it = 0; it < 2; it++) \
        CP16(base_ + a_soff[it], Ap + a_gidx[it] + (size_t)(KC) * 32); \
    _Pragma("unroll") \
    for (int it = 0; it < 2; it++) \
        CP16(base_ + b_soff[it], Bp + b_gidx[it] + (size_t)(KC) * 32 * N_TOTAL); \
} while (0)

#define COMPUTE(BS) do { \
    uint32_t base_ = sbase + (uint32_t)(BS) * (BUF * 2); \
    _Pragma("unroll") \
    for (int kt = 0; kt < 2; kt++) { \
        uint32_t ah[2][4]; \
        _Pragma("unroll") \
        for (int mt = 0; mt < 2; mt++) { \
            uint32_t ad = base_ + 2u * (aoff + (uint32_t)(mt * 640 + kt * 16)); \
            LDSM_X4(ah[mt], ad); \
        } \
        uint32_t bh[8][2]; \
        _Pragma("unroll") \
        for (int bt = 0; bt < 4; bt++) { \
            uint32_t bd = base_ + 2u * ((uint32_t)A_SZ + boff \
                                        + (uint32_t)(bt * 16 + kt * 16 * 136)); \
            LDSM_X4T(bh[bt * 2][0], bh[bt * 2][1], bh[bt * 2 + 1][0], bh[bt * 2 + 1][1], bd); \
        } \
        _Pragma("unroll") \
        for (int mt = 0; mt < 2; mt++) { \
            _Pragma("unroll") \
            for (int nt = 0; nt < 8; nt++) \
                MMA_F16(c[mt * 8 + nt], ah[mt], bh[nt]); \
        } \
    } \
} while (0)

    // ---- 4-stage cp.async pipeline ----
    ISSUE(0, 0); CP_COMMIT();
    ISSUE(1, 1); CP_COMMIT();
    ISSUE(2, 2); CP_COMMIT();
    for (int kc = 0; kc < NC; kc++) {
        if (kc < NC - 2)       { CP_WAIT(2); }
        else if (kc == NC - 2) { CP_WAIT(1); }
        else                   { CP_WAIT(0); }
        __syncthreads();
        if (kc + 3 < NC) { ISSUE(kc + 3, (kc + 3) & 3); CP_COMMIT(); }
        COMPUTE(kc & 3);
    }

#undef ISSUE
#undef COMPUTE

    // ---- epilogue ----
    const float* bp = bias + (size_t)e * N_TOTAL + n0;
    const int rbase = m0 + wm + (lane >> 2);
#pragma unroll
    for (int mt = 0; mt < 2; mt++) {
#pragma unroll
        for (int nt = 0; nt < 8; nt++) {
            float* cc = c[mt * 8 + nt];
            int col = wn + nt * 8 + 2 * (lane & 3);
            float2 bb = *reinterpret_cast<const float2*>(bp + col);
#pragma unroll
            for (int h = 0; h < 2; h++) {
                int r = rbase + mt * 16 + h * 8;
                if (r < seg_count) {
                    float v0 = cc[h * 2 + 0] + bb.x;
                    float v1 = cc[h * 2 + 1] + bb.y;
                    if (IS1) {
                        v0 = fmaxf(v0, 0.0f);
                        v1 = fmaxf(v1, 0.0f);
                        __half2 hv = __floats2half2_rn(v0, v1);
                        size_t off = (size_t)(seg_start + r) * DF + n0 + col;
                        *reinterpret_cast<uint32_t*>(g_Y1 + off) =
                            *reinterpret_cast<uint32_t*>(&hv);
                    } else {
                        int grow = seg_start + r;
                        int tok  = g_row_tok[grow];
                        float gg = g_row_gate[grow];
                        float* po = out + (size_t)tok * DM + n0 + col;
                        atomicAdd(po,     gg * v0);
                        atomicAdd(po + 1, gg * v1);
                    }
                }
            }
        }
    }
}

// ---------------- launch ------------------------------------------------------
extern "C" void kernel_launch(void* const* d_in, const int* in_sizes, int n_in,
                              void* d_out, int out_size) {
    const float* x  = (const float*)d_in[0];
    const float* Wg = (const float*)d_in[1];
    const float* bg = (const float*)d_in[2];
    const float* W1 = (const float*)d_in[3];
    const float* b1 = (const float*)d_in[4];
    const float* W2 = (const float*)d_in[5];
    const float* b2 = (const float*)d_in[6];
    float* out = (float*)d_out;

    constexpr int SMEM = 4 * (128 * 40 + 32 * 136) * 2;   // 75776
    cudaFuncSetAttribute(moe_mma<DM, DF, 1>,
                         cudaFuncAttributeMaxDynamicSharedMemorySize, SMEM);
    cudaFuncSetAttribute(moe_mma<DF, DM, 0>,
                         cudaFuncAttributeMaxDynamicSharedMemorySize, SMEM);

    void* p_ctrl;
    cudaGetSymbolAddress(&p_ctrl, g_ctrl);
    cudaMemsetAsync(p_ctrl, 0, 2 * NE * sizeof(int));

    gatecvt_kernel<<<GATE_BLKS + CVT_BLKS, 256>>>(x, Wg, bg, W1, W2, out);
    prefix_kernel<<<1, 32>>>();
    scatter_kernel<<<NPAIRS / 256, 256>>>();
    gatherx_kernel<<<NPAIRS / 2, 256>>>(x);

    dim3 grid1(72, DF / 128);    // exact tile table, M=128
    moe_mma<DM, DF, 1><<<grid1, 256, SMEM>>>(b1, out);

    dim3 grid2(72, DM / 128);    // fused combine epilogue
    moe_mma<DF, DM, 0><<<grid2, 256, SMEM>>>(b2, out);
}

// round 13
// speedup vs baseline: 1.4257x; 1.0640x over previous
#include <cuda_runtime.h>
#include <cuda_fp16.h>
#include <cstdint>

#define T_TOKENS 4096
#define DM 512
#define NE 8
#define DF 2048
#define NPAIRS (T_TOKENS * 2)
#define CAP 8192      // fixed per-expert segment capacity (worst case)
#define MAX_T 80      // >= NPAIRS/128 + NE

// ---------------- device scratch ------------------------------------------
__device__ int   g_ctrl[NE];                      // per-expert pair counts
__device__ int   g_row_tok[NE * CAP];
__device__ float g_row_gate[NE * CAP];
__device__ int2  g_tiles[MAX_T];
__device__ int   g_nt;
__device__ __half g_xg[(size_t)NE * CAP * DM];    // 64 MiB fixed-base gathered x
__device__ __half g_Y1[(size_t)NE * CAP * DF];    // 256 MiB fixed-base Y1
__device__ __half g_W1h[(size_t)NE * DM * DF];    // 16 MiB
__device__ __half g_W2h[(size_t)NE * DF * DM];    // 16 MiB

// ---------------- helpers ----------------------------------------------------
#define LDSM_X4(R, ADDR) \
    asm volatile("ldmatrix.sync.aligned.m8n8.x4.shared.b16 {%0,%1,%2,%3}, [%4];" \
        : "=r"((R)[0]), "=r"((R)[1]), "=r"((R)[2]), "=r"((R)[3]) : "r"(ADDR))

#define LDSM_X4T(R0, R1, R2, R3, ADDR) \
    asm volatile("ldmatrix.sync.aligned.m8n8.x4.trans.shared.b16 {%0,%1,%2,%3}, [%4];" \
        : "=r"(R0), "=r"(R1), "=r"(R2), "=r"(R3) : "r"(ADDR))

#define MMA_F16(C, A, B) \
    asm volatile("mma.sync.aligned.m16n8k16.row.col.f32.f16.f16.f32 " \
        "{%0,%1,%2,%3}, {%4,%5,%6,%7}, {%8,%9}, {%0,%1,%2,%3};" \
        : "+f"((C)[0]), "+f"((C)[1]), "+f"((C)[2]), "+f"((C)[3]) \
        : "r"((A)[0]), "r"((A)[1]), "r"((A)[2]), "r"((A)[3]), \
          "r"((B)[0]), "r"((B)[1]))

#define CP16(DST, SRC) \
    asm volatile("cp.async.cg.shared.global [%0], [%1], 16;" \
        :: "r"(DST), "l"(SRC))
#define CP_COMMIT() asm volatile("cp.async.commit_group;")
#define CP_WAIT(N)  asm volatile("cp.async.wait_group %0;" :: "n"(N))

__device__ __forceinline__ void cvt4(const float* srcp, __half* dst) {
    float4 v = *reinterpret_cast<const float4*>(srcp);
    __half2 a = __floats2half2_rn(v.x, v.y);
    __half2 b = __floats2half2_rn(v.z, v.w);
    uint2 o;
    o.x = *reinterpret_cast<uint32_t*>(&a);
    o.y = *reinterpret_cast<uint32_t*>(&b);
    *reinterpret_cast<uint2*>(dst) = o;
}

// ---------------- gate+slot+gather (blocks 0..511) + W convert (rest) -------
// Gate blocks: zero 8 out rows, compute logits, top-2, assign fixed-base slots,
// and convert/store the token's x row to both assigned g_xg rows.
#define GATE_BLKS 512
#define CVT_BLKS  ((2 * NE * DM * DF / 4) / 256)   // 16384

__global__ __launch_bounds__(256)
void gatecvt_kernel(const float* __restrict__ x,
                    const float* __restrict__ Wg,
                    const float* __restrict__ bg,
                    const float* __restrict__ W1,
                    const float* __restrict__ W2,
                    float* __restrict__ out) {
    const int bid = blockIdx.x;
    if (bid >= GATE_BLKS) {
        constexpr int NW = NE * DM * DF / 4;
        int idx = (bid - GATE_BLKS) * 256 + threadIdx.x;
        if (idx < NW) cvt4(W1 + (size_t)idx * 4, g_W1h + (size_t)idx * 4);
        else          cvt4(W2 + (size_t)(idx - NW) * 4, g_W2h + (size_t)(idx - NW) * 4);
        return;
    }

    // zero this block's 8 output token rows (1024 float4)
    {
        float4 z; z.x = z.y = z.z = z.w = 0.0f;
        float4* ob = reinterpret_cast<float4*>(out) + (size_t)bid * 1024;
#pragma unroll
        for (int i = 0; i < 4; i++) ob[threadIdx.x + 256 * i] = z;
    }

    __shared__ float sWgT[NE * DM];   // transposed [e][d]
    for (int i = threadIdx.x; i < DM * NE; i += blockDim.x) {
        int d = i >> 3, e = i & 7;
        sWgT[e * DM + d] = Wg[i];
    }
    __syncthreads();

    int warp = threadIdx.x >> 5, lane = threadIdx.x & 31;
    int t = bid * 8 + warp;
    const float* xr = x + (size_t)t * DM;

    float lg[NE];
#pragma unroll
    for (int e = 0; e < NE; e++) lg[e] = 0.0f;
#pragma unroll
    for (int i = 0; i < DM / 32; i++) {
        int d = lane + 32 * i;
        float xv = xr[d];
#pragma unroll
        for (int e = 0; e < NE; e++)
            lg[e] = fmaf(xv, sWgT[e * DM + d], lg[e]);
    }
#pragma unroll
    for (int off = 16; off > 0; off >>= 1)
#pragma unroll
        for (int e = 0; e < NE; e++)
            lg[e] += __shfl_xor_sync(0xFFFFFFFFu, lg[e], off);

    int row0 = 0, row1 = 0;
    if (lane == 0) {
#pragma unroll
        for (int e = 0; e < NE; e++) lg[e] += bg[e];
        int i0 = 0;
#pragma unroll
        for (int e = 1; e < NE; e++) if (lg[e] > lg[i0]) i0 = e;
        int i1 = (i0 == 0) ? 1 : 0;
#pragma unroll
        for (int e = 0; e < NE; e++)
            if (e != i0 && lg[e] > lg[i1]) i1 = e;
        float g0 = 1.0f / (1.0f + expf(lg[i1] - lg[i0]));
        float g1 = 1.0f - g0;
        int pos0 = atomicAdd(&g_ctrl[i0], 1);
        int pos1 = atomicAdd(&g_ctrl[i1], 1);
        row0 = i0 * CAP + pos0;
        row1 = i1 * CAP + pos1;
        g_row_tok[row0]  = t;  g_row_gate[row0] = g0;
        g_row_tok[row1]  = t;  g_row_gate[row1] = g1;
    }
    row0 = __shfl_sync(0xFFFFFFFFu, row0, 0);
    row1 = __shfl_sync(0xFFFFFFFFu, row1, 0);

    // convert this token's x row once (L1-hot), store to both g_xg rows
    const float4* xr4 = reinterpret_cast<const float4*>(xr);
#pragma unroll
    for (int i = 0; i < DM / 128; i++) {           // 4 float4 per lane
        int c4 = lane + 32 * i;
        float4 v = xr4[c4];
        __half2 a = __floats2half2_rn(v.x, v.y);
        __half2 b = __floats2half2_rn(v.z, v.w);
        uint2 o;
        o.x = *reinterpret_cast<uint32_t*>(&a);
        o.y = *reinterpret_cast<uint32_t*>(&b);
        *reinterpret_cast<uint2*>(g_xg + (size_t)row0 * DM + (size_t)c4 * 4) = o;
        *reinterpret_cast<uint2*>(g_xg + (size_t)row1 * DM + (size_t)c4 * 4) = o;
    }
}

// ---------------- tile table from counts (no prefix needed) ------------------
__global__ void tiles_kernel() {
    if (threadIdx.x != 0) return;
    int n = 0;
    for (int e = 0; e < NE; e++)
        for (int m0 = 0; m0 < g_ctrl[e]; m0 += 128) {
            int2 v; v.x = e; v.y = m0; g_tiles[n++] = v;
        }
    g_nt = n;
}

// ---------------- fp16 HMMA grouped GEMM (round-7 proven code) ---------------
// CTA tile 128x128, BK=32, 256 threads, warp tile 32x64, cp.async 4-stage,
// 2 CTAs/SM.  Fixed-base segments: seg_start = e*CAP.
// IS1=1: Y1 = relu(g_xg@W1+b1) fp16.
// IS1=0: out[token] += gate * (Y1@W2 + b2) via atomicAdd (fused combine).
template<int K_TOTAL, int N_TOTAL, int IS1>
__global__ __launch_bounds__(256, 2)
void moe_mma(const float* __restrict__ bias, float* __restrict__ out)
{
    constexpr int NC   = K_TOTAL / 32;
    constexpr int A_SZ = 128 * 40;               // elems
    constexpr int B_SZ = 32 * 136;               // elems
    constexpr int BUF  = A_SZ + B_SZ;            // 9472 elems

    if (blockIdx.x >= g_nt) return;
    const int2 te = g_tiles[blockIdx.x];
    const int e = te.x, m0 = te.y;
    const int seg_start = e * CAP;
    const int seg_count = g_ctrl[e];
    const int n0 = blockIdx.y * 128;

    const int tid  = threadIdx.x;
    const int lane = tid & 31;
    const int warp = tid >> 5;
    const int wm = (warp & 3) * 32;
    const int wn = (warp >> 2) * 64;

    extern __shared__ __half smraw[];
    const uint32_t sbase = (uint32_t)__cvta_generic_to_shared(smraw);

    const __half* Ap = IS1 ? g_xg : g_Y1;
    const __half* Bp = (IS1 ? g_W1h : g_W2h)
                       + (size_t)e * K_TOTAL * N_TOTAL + n0;

    uint32_t a_soff[2];
    size_t   a_gidx[2];
#pragma unroll
    for (int it = 0; it < 2; it++) {
        int u = tid + it * 256;                  // 512 int4 per A tile
        int r = m0 + (u >> 2);
        if (r >= seg_count) r = seg_count - 1;
        a_soff[it] = (uint32_t)((u >> 2) * 40 + (u & 3) * 8) * 2;
        a_gidx[it] = (size_t)(seg_start + r) * K_TOTAL + (u & 3) * 8;
    }
    uint32_t b_soff[2];
    size_t   b_gidx[2];
#pragma unroll
    for (int it = 0; it < 2; it++) {
        int v = tid + it * 256;                  // 512 int4 for B
        int bk = v >> 4, bn = (v & 15) * 8;
        b_soff[it] = (uint32_t)(A_SZ + bk * 136 + bn) * 2;
        b_gidx[it] = (size_t)bk * N_TOTAL + bn;
    }

    const uint32_t aoff = (uint32_t)((wm + (lane & 15)) * 40 + (lane >> 4) * 8);
    const uint32_t boff = (uint32_t)((((lane >> 3) & 1) * 8 + (lane & 7)) * 136
                                     + wn + (lane >> 4) * 8);

    float c[16][4];
#pragma unroll
    for (int f = 0; f < 16; f++)
#pragma unroll
        for (int q = 0; q < 4; q++) c[f][q] = 0.0f;

#define ISSUE(KC, BS) do { \
    uint32_t base_ = sbase + (uint32_t)(BS) * (BUF * 2); \
    _Pragma("unroll") \
    for (int it = 0; it < 2; it++) \
        CP16(base_ + a_soff[it], Ap + a_gidx[it] + (size_t)(KC) * 32); \
    _Pragma("unroll") \
    for (int it = 0; it < 2; it++) \
        CP16(base_ + b_soff[it], Bp + b_gidx[it] + (size_t)(KC) * 32 * N_TOTAL); \
} while (0)

#define COMPUTE(BS) do { \
    uint32_t base_ = sbase + (uint32_t)(BS) * (BUF * 2); \
    _Pragma("unroll") \
    for (int kt = 0; kt < 2; kt++) { \
        uint32_t ah[2][4]; \
        _Pragma("unroll") \
        for (int mt = 0; mt < 2; mt++) { \
            uint32_t ad = base_ + 2u * (aoff + (uint32_t)(mt * 640 + kt * 16)); \
            LDSM_X4(ah[mt], ad); \
        } \
        uint32_t bh[8][2]; \
        _Pragma("unroll") \
        for (int bt = 0; bt < 4; bt++) { \
            uint32_t bd = base_ + 2u * ((uint32_t)A_SZ + boff \
                                        + (uint32_t)(bt * 16 + kt * 16 * 136)); \
            LDSM_X4T(bh[bt * 2][0], bh[bt * 2][1], bh[bt * 2 + 1][0], bh[bt * 2 + 1][1], bd); \
        } \
        _Pragma("unroll") \
        for (int mt = 0; mt < 2; mt++) { \
            _Pragma("unroll") \
            for (int nt = 0; nt < 8; nt++) \
                MMA_F16(c[mt * 8 + nt], ah[mt], bh[nt]); \
        } \
    } \
} while (0)

    // ---- 4-stage cp.async pipeline ----
    ISSUE(0, 0); CP_COMMIT();
    ISSUE(1, 1); CP_COMMIT();
    ISSUE(2, 2); CP_COMMIT();
    for (int kc = 0; kc < NC; kc++) {
        if (kc < NC - 2)       { CP_WAIT(2); }
        else if (kc == NC - 2) { CP_WAIT(1); }
        else                   { CP_WAIT(0); }
        __syncthreads();
        if (kc + 3 < NC) { ISSUE(kc + 3, (kc + 3) & 3); CP_COMMIT(); }
        COMPUTE(kc & 3);
    }

#undef ISSUE
#undef COMPUTE

    // ---- epilogue ----
    const float* bp = bias + (size_t)e * N_TOTAL + n0;
    const int rbase = m0 + wm + (lane >> 2);
#pragma unroll
    for (int mt = 0; mt < 2; mt++) {
#pragma unroll
        for (int nt = 0; nt < 8; nt++) {
            float* cc = c[mt * 8 + nt];
            int col = wn + nt * 8 + 2 * (lane & 3);
            float2 bb = *reinterpret_cast<const float2*>(bp + col);
#pragma unroll
            for (int h = 0; h < 2; h++) {
                int r = rbase + mt * 16 + h * 8;
                if (r < seg_count) {
                    float v0 = cc[h * 2 + 0] + bb.x;
                    float v1 = cc[h * 2 + 1] + bb.y;
                    if (IS1) {
                        v0 = fmaxf(v0, 0.0f);
                        v1 = fmaxf(v1, 0.0f);
                        __half2 hv = __floats2half2_rn(v0, v1);
                        size_t off = (size_t)(seg_start + r) * DF + n0 + col;
                        *reinterpret_cast<uint32_t*>(g_Y1 + off) =
                            *reinterpret_cast<uint32_t*>(&hv);
                    } else {
                        int grow = seg_start + r;
                        int tok  = g_row_tok[grow];
                        float gg = g_row_gate[grow];
                        float* po = out + (size_t)tok * DM + n0 + col;
                        atomicAdd(po,     gg * v0);
                        atomicAdd(po + 1, gg * v1);
                    }
                }
            }
        }
    }
}

// ---------------- launch ------------------------------------------------------
extern "C" void kernel_launch(void* const* d_in, const int* in_sizes, int n_in,
                              void* d_out, int out_size) {
    const float* x  = (const float*)d_in[0];
    const float* Wg = (const float*)d_in[1];
    const float* bg = (const float*)d_in[2];
    const float* W1 = (const float*)d_in[3];
    const float* b1 = (const float*)d_in[4];
    const float* W2 = (const float*)d_in[5];
    const float* b2 = (const float*)d_in[6];
    float* out = (float*)d_out;

    constexpr int SMEM = 4 * (128 * 40 + 32 * 136) * 2;   // 75776
    cudaFuncSetAttribute(moe_mma<DM, DF, 1>,
                         cudaFuncAttributeMaxDynamicSharedMemorySize, SMEM);
    cudaFuncSetAttribute(moe_mma<DF, DM, 0>,
                         cudaFuncAttributeMaxDynamicSharedMemorySize, SMEM);

    void* p_ctrl;
    cudaGetSymbolAddress(&p_ctrl, g_ctrl);
    cudaMemsetAsync(p_ctrl, 0, NE * sizeof(int));

    gatecvt_kernel<<<GATE_BLKS + CVT_BLKS, 256>>>(x, Wg, bg, W1, W2, out);
    tiles_kernel<<<1, 32>>>();

    dim3 grid1(72, DF / 128);    // exact tile table, M=128
    moe_mma<DM, DF, 1><<<grid1, 256, SMEM>>>(b1, out);

    dim3 grid2(72, DM / 128);    // fused combine epilogue
    moe_mma<DF, DM, 0><<<grid2, 256, SMEM>>>(b2, out);
}